// round 10
// baseline (speedup 1.0000x reference)
#include <cuda_runtime.h>
#include <cuda_fp16.h>
#include <cstdint>
#include <math.h>

#define Tn 8192
#define Sn 1024
#define Bn 8
#define Hn 8
#define Un 64
#define Dn 512
#define Fn 2048

// ---------------- scratch ----------------------------------------------------
__device__ __half g_xh[(size_t)Tn * Dn];
__device__ __half g_qwT[(size_t)Hn * Un * Dn];
__device__ __half g_kwT[(size_t)Hn * Un * Dn];
__device__ __half g_vwT[(size_t)Hn * Dn * Dn];
__device__ __half g_lwT[(size_t)Dn * Hn * Dn];
__device__ __half g_w1T[(size_t)Fn * Dn];
__device__ __half g_w2T[(size_t)Dn * Fn];
__device__ __half g_Q[(size_t)Hn * Tn * Un];
__device__ __half g_K[(size_t)Hn * Tn * Un];
__device__ __half g_VT[(size_t)Hn * Dn * Tn];
__device__ float  g_S[(size_t)Hn * Bn * Sn * Sn];
__device__ __half g_P[(size_t)Hn * Bn * Sn * Sn];
__device__ __half g_Ac[(size_t)Tn * Hn * Dn];
__device__ float  g_mha[(size_t)Tn * Dn];
__device__ float  g_hb[(size_t)Tn * Dn];
__device__ __half g_hbh[(size_t)Tn * Dn];
__device__ __half g_f1[(size_t)Tn * Fn];
__device__ float  g_f2[(size_t)Tn * Dn];

// ---------------- helpers ----------------------------------------------------
__device__ __forceinline__ uint32_t smem_u32(const void* p) {
    uint32_t a;
    asm("{ .reg .u64 t; cvta.to.shared.u64 t, %1; cvt.u32.u64 %0, t; }"
        : "=r"(a) : "l"(p));
    return a;
}
__device__ __forceinline__ void cp_async16(uint32_t s, const void* g) {
    asm volatile("cp.async.cg.shared.global [%0], [%1], 16;\n" :: "r"(s), "l"(g));
}
__device__ __forceinline__ void cp_commit() {
    asm volatile("cp.async.commit_group;\n" ::);
}
__device__ __forceinline__ void cp_wait2() {
    asm volatile("cp.async.wait_group 2;\n" ::);
}
__device__ __forceinline__ void ldsm4(uint32_t* r, uint32_t addr) {
    asm volatile("ldmatrix.sync.aligned.m8n8.x4.shared.b16 {%0,%1,%2,%3}, [%4];"
                 : "=r"(r[0]), "=r"(r[1]), "=r"(r[2]), "=r"(r[3]) : "r"(addr));
}
__device__ __forceinline__ void mma16816(float* c, const uint32_t* a,
                                         uint32_t b0, uint32_t b1) {
    asm volatile(
        "mma.sync.aligned.m16n8k16.row.col.f32.f16.f16.f32 "
        "{%0,%1,%2,%3}, {%4,%5,%6,%7}, {%8,%9}, {%0,%1,%2,%3};"
        : "+f"(c[0]), "+f"(c[1]), "+f"(c[2]), "+f"(c[3])
        : "r"(a[0]), "r"(a[1]), "r"(a[2]), "r"(a[3]), "r"(b0), "r"(b1));
}

// ---------------- pipelined fp16 HMMA GEMM -----------------------------------
// C[m,n] = alpha * sum_k A[m,k]*B[n,k] (+bias[n]) (opt relu).
// A,B fp16 row-major. M%128==0, N%TSN==0, K%32==0. 256 thr, warps 2m x 4n,
// warp tile 64 x (TSN/4). 4-stage cp.async ring, one __syncthreads per k-tile.
#define RSTR 80   // smem row stride bytes (64B data + 16B pad)

template <int TSN, bool OUTH, bool BIAS, bool RELU>
__global__ __launch_bounds__(256, 1) void pgemm(
    const __half* __restrict__ A_, const __half* __restrict__ B_,
    const float* __restrict__ bias, float* __restrict__ Cf,
    __half* __restrict__ Ch,
    int K, int lda, int ldb, int ldc,
    long long sAh, long long sAb, long long sBh, long long sBb,
    long long sCh, long long sCb, int bdiv, float alpha)
{
    constexpr int WN = TSN / 4;       // 64 or 16
    constexpr int NT = WN / 8;        // 8 or 2
    constexpr int ABYT = 128 * RSTR;
    constexpr int BBYT = TSN * RSTR;
    constexpr int STAGE = ABYT + BBYT;

    extern __shared__ char sm[];
    uint32_t sb = smem_u32(sm);

    int tid = threadIdx.x, lane = tid & 31, wid = tid >> 5;
    int wm = wid & 1, wn = wid >> 1;

    int z = blockIdx.z;
    int h = z / bdiv, b = z % bdiv;
    const __half* Ab = A_ + h * sAh + b * sAb;
    const __half* Bb = B_ + h * sBh + b * sBb;

    long long m0 = (long long)blockIdx.y * 128;
    int n0 = blockIdx.x * TSN;

    // staging maps: A 128 rows x 64B
    int arow = tid >> 1;
    uint32_t aoff = arow * RSTR + (tid & 1) * 32;
    const __half* gA = Ab + (m0 + arow) * (long long)lda + (tid & 1) * 16;
    // B: TSN rows x 64B
    uint32_t boff;
    const __half* gB;
    if (TSN == 256) {
        boff = ABYT + tid * RSTR;
        gB = Bb + (long long)(n0 + tid) * ldb;
    } else {  // TSN == 64
        int brow = tid >> 2;
        boff = ABYT + brow * RSTR + (tid & 3) * 16;
        gB = Bb + (long long)(n0 + brow) * ldb + (tid & 3) * 8;
    }

    int lrow = lane & 15, lhalf = lane >> 4;
    uint32_t pAo = (wm * 64 + lrow) * RSTR + lhalf * 16;
    uint32_t pBo = ABYT + (wn * WN + lrow) * RSTR + lhalf * 16;

    float acc[4][NT][4];
#pragma unroll
    for (int i = 0; i < 4; i++)
#pragma unroll
        for (int j = 0; j < NT; j++)
#pragma unroll
            for (int q = 0; q < 4; q++) acc[i][j][q] = 0.0f;

    int ktiles = K / 32;

    auto load_stage = [&](int ktl, uint32_t sd) {
        long long ko = (long long)ktl * 32;
        cp_async16(sd + aoff, gA + ko);
        cp_async16(sd + aoff + 16, gA + ko + 8);
        if (TSN == 256) {
#pragma unroll
            for (int q = 0; q < 4; q++)
                cp_async16(sd + boff + q * 16, gB + ko + q * 8);
        } else {
            cp_async16(sd + boff, gB + ko);
        }
    };

    load_stage(0, sb);
    cp_commit();
    if (ktiles > 1) load_stage(1, sb + STAGE);
    cp_commit();

    for (int kt = 0; kt < ktiles; kt++) {
        int buf = kt & 3;
        if (kt + 2 < ktiles) load_stage(kt + 2, sb + ((kt + 2) & 3) * STAGE);
        cp_commit();
        cp_wait2();
        __syncthreads();

        uint32_t pA = sb + buf * STAGE + pAo;
        uint32_t pB = sb + buf * STAGE + pBo;
#pragma unroll
        for (int ks = 0; ks < 2; ks++) {
            uint32_t af[4][4];
#pragma unroll
            for (int mt = 0; mt < 4; mt++)
                ldsm4(af[mt], pA + mt * 16 * RSTR + ks * 32);
            uint32_t bf[NT / 2][4];
#pragma unroll
            for (int np = 0; np < NT / 2; np++)
                ldsm4(bf[np], pB + np * 16 * RSTR + ks * 32);
#pragma unroll
            for (int mt = 0; mt < 4; mt++)
#pragma unroll
                for (int np = 0; np < NT / 2; np++) {
                    mma16816(acc[mt][2 * np], af[mt], bf[np][0], bf[np][2]);
                    mma16816(acc[mt][2 * np + 1], af[mt], bf[np][1], bf[np][3]);
                }
        }
        // buffer reused 4 iterations later; syncthreads above suffices
    }

    // epilogue
    int g = lane >> 2, c2 = (lane & 3) * 2;
    long long hoff = h * sCh + b * sCb;
#pragma unroll
    for (int mt = 0; mt < 4; mt++) {
        long long r0 = m0 + wm * 64 + mt * 16 + g;
#pragma unroll
        for (int nt = 0; nt < NT; nt++) {
            int col = n0 + wn * WN + nt * 8 + c2;
            float v0 = acc[mt][nt][0] * alpha, v1 = acc[mt][nt][1] * alpha;
            float v2 = acc[mt][nt][2] * alpha, v3 = acc[mt][nt][3] * alpha;
            if (BIAS) {
                float b0 = bias[col], b1 = bias[col + 1];
                v0 += b0; v1 += b1; v2 += b0; v3 += b1;
            }
            if (RELU) {
                v0 = fmaxf(v0, 0.f); v1 = fmaxf(v1, 0.f);
                v2 = fmaxf(v2, 0.f); v3 = fmaxf(v3, 0.f);
            }
            if (OUTH) {
                *(__half2*)(Ch + hoff + r0 * ldc + col) = __floats2half2_rn(v0, v1);
                *(__half2*)(Ch + hoff + (r0 + 8) * ldc + col) = __floats2half2_rn(v2, v3);
            } else {
                float2 o0 = {v0, v1}, o1 = {v2, v3};
                *(float2*)(Cf + hoff + r0 * ldc + col) = o0;
                *(float2*)(Cf + hoff + (r0 + 8) * ldc + col) = o1;
            }
        }
    }
}

// ---------------- elementwise convert: fp32 -> fp16 --------------------------
__global__ __launch_bounds__(256) void cvt_kernel(
    const float* __restrict__ in, __half* __restrict__ o)
{
    long long i = (long long)blockIdx.x * 256 + threadIdx.x;
    float4 v = reinterpret_cast<const float4*>(in)[i];
    reinterpret_cast<__half2*>(o)[2 * i] = __floats2half2_rn(v.x, v.y);
    reinterpret_cast<__half2*>(o)[2 * i + 1] = __floats2half2_rn(v.z, v.w);
}

// ---------------- transpose+convert [Z][R][C] -> fp16 [Z][C][R] --------------
__global__ __launch_bounds__(256) void tc_kernel(
    const float* __restrict__ in, __half* __restrict__ o, int R, int C)
{
    __shared__ float t[32][33];
    const float* ib = in + (long long)blockIdx.z * R * C;
    long long ob = (long long)blockIdx.z * R * C;
    int c0 = blockIdx.x * 32, r0 = blockIdx.y * 32;
    int x = threadIdx.x, y = threadIdx.y;
#pragma unroll
    for (int i = 0; i < 32; i += 8)
        t[y + i][x] = ib[(long long)(r0 + y + i) * C + c0 + x];
    __syncthreads();
#pragma unroll
    for (int i = 0; i < 32; i += 8)
        o[ob + (long long)(c0 + y + i) * R + r0 + x] = __float2half_rn(t[x][y + i]);
}

// ---------------- softmax (row=1024) -> fp16, __expf + shuffle reductions ----
__global__ __launch_bounds__(256) void softmax_kernel(
    const float* __restrict__ S, __half* __restrict__ P)
{
    long long row = blockIdx.x;
    const float4* p = reinterpret_cast<const float4*>(S + row * Sn);
    int tid = threadIdx.x, lane = tid & 31, wid = tid >> 5;
    float4 v = p[tid];
    __shared__ float wred[8];

    float m = fmaxf(fmaxf(v.x, v.y), fmaxf(v.z, v.w));
#pragma unroll
    for (int o = 16; o; o >>= 1)
        m = fmaxf(m, __shfl_xor_sync(0xffffffffu, m, o));
    if (lane == 0) wred[wid] = m;
    __syncthreads();
    float rmax = wred[0];
#pragma unroll
    for (int i = 1; i < 8; i++) rmax = fmaxf(rmax, wred[i]);
    __syncthreads();

    v.x = __expf(v.x - rmax); v.y = __expf(v.y - rmax);
    v.z = __expf(v.z - rmax); v.w = __expf(v.w - rmax);
    float s = v.x + v.y + v.z + v.w;
#pragma unroll
    for (int o = 16; o; o >>= 1)
        s += __shfl_xor_sync(0xffffffffu, s, o);
    if (lane == 0) wred[wid] = s;
    __syncthreads();
    float tot = wred[0];
#pragma unroll
    for (int i = 1; i < 8; i++) tot += wred[i];

    float inv = __fdividef(1.0f, tot);
    __half2* ph = reinterpret_cast<__half2*>(P + row * Sn);
    ph[2 * tid] = __floats2half2_rn(v.x * inv, v.y * inv);
    ph[2 * tid + 1] = __floats2half2_rn(v.z * inv, v.w * inv);
}

// ---------------- residual add + LayerNorm (row=512), shuffle reductions -----
template <bool EMIT>
__global__ __launch_bounds__(128) void add_ln_kernel(
    const float* __restrict__ X, const float* __restrict__ Y,
    const float* __restrict__ gamma, const float* __restrict__ beta,
    float* __restrict__ out, __half* __restrict__ oh)
{
    long long row = blockIdx.x;
    int tid = threadIdx.x, lane = tid & 31, wid = tid >> 5;
    const float4* x4 = reinterpret_cast<const float4*>(X + row * Dn);
    const float4* y4 = reinterpret_cast<const float4*>(Y + row * Dn);
    float4 a = x4[tid], c = y4[tid];
    float v0 = a.x + c.x, v1 = a.y + c.y, v2 = a.z + c.z, v3 = a.w + c.w;
    __shared__ float ws[4], wq[4];
    float s = v0 + v1 + v2 + v3;
    float q = v0 * v0 + v1 * v1 + v2 * v2 + v3 * v3;
#pragma unroll
    for (int o = 16; o; o >>= 1) {
        s += __shfl_xor_sync(0xffffffffu, s, o);
        q += __shfl_xor_sync(0xffffffffu, q, o);
    }
    if (lane == 0) { ws[wid] = s; wq[wid] = q; }
    __syncthreads();
    float rs = ws[0] + ws[1] + ws[2] + ws[3];
    float rq = wq[0] + wq[1] + wq[2] + wq[3];
    float mean = rs * (1.0f / Dn);
    float var = rq * (1.0f / Dn) - mean * mean;
    float rstd = rsqrtf(var + 1e-3f);
    float4 g = reinterpret_cast<const float4*>(gamma)[tid];
    float4 bb = reinterpret_cast<const float4*>(beta)[tid];
    float4 o;
    o.x = g.x * (v0 - mean) * rstd + bb.x;
    o.y = g.y * (v1 - mean) * rstd + bb.y;
    o.z = g.z * (v2 - mean) * rstd + bb.z;
    o.w = g.w * (v3 - mean) * rstd + bb.w;
    reinterpret_cast<float4*>(out + row * Dn)[tid] = o;
    if (EMIT) {
        __half2* ph = reinterpret_cast<__half2*>(oh + row * Dn);
        ph[2 * tid] = __floats2half2_rn(o.x, o.y);
        ph[2 * tid + 1] = __floats2half2_rn(o.z, o.w);
    }
}

// ---------------- launch -----------------------------------------------------
extern "C" void kernel_launch(void* const* d_in, const int* in_sizes, int n_in,
                              void* d_out, int out_size)
{
    const float* x  = (const float*)d_in[0];
    const float* qw = (const float*)d_in[1];
    const float* kw = (const float*)d_in[2];
    const float* vw = (const float*)d_in[3];
    const float* lw = (const float*)d_in[4];
    const float* g1 = (const float*)d_in[5];
    const float* b1v= (const float*)d_in[6];
    const float* w1 = (const float*)d_in[7];
    const float* bb1= (const float*)d_in[8];
    const float* w2 = (const float*)d_in[9];
    const float* bb2= (const float*)d_in[10];
    const float* g2 = (const float*)d_in[11];
    const float* b2v= (const float*)d_in[12];
    float* out = (float*)d_out;

#define GA(p, s) cudaGetSymbolAddress((void**)&p, s)
    __half *xh, *qwT, *kwT, *vwT, *lwT, *w1T, *w2T;
    __half *Q, *K, *VT, *P, *Ac, *hbh, *f1;
    float *S, *mha, *hb, *f2;
    GA(xh, g_xh);
    GA(qwT, g_qwT); GA(kwT, g_kwT); GA(vwT, g_vwT); GA(lwT, g_lwT);
    GA(w1T, g_w1T); GA(w2T, g_w2T);
    GA(Q, g_Q); GA(K, g_K); GA(VT, g_VT);
    GA(P, g_P); GA(Ac, g_Ac); GA(hbh, g_hbh); GA(f1, g_f1);
    GA(S, g_S); GA(mha, g_mha); GA(hb, g_hb); GA(f2, g_f2);
#undef GA

    constexpr int SMBIG = 4 * (128 * RSTR + 256 * RSTR); // 122880
    constexpr int SM64  = 4 * (128 * RSTR + 64 * RSTR);  // 61440
    cudaFuncSetAttribute(pgemm<64, true, false, false>,
                         cudaFuncAttributeMaxDynamicSharedMemorySize, SM64);
    cudaFuncSetAttribute(pgemm<256, true, false, false>,
                         cudaFuncAttributeMaxDynamicSharedMemorySize, SMBIG);
    cudaFuncSetAttribute(pgemm<256, false, false, false>,
                         cudaFuncAttributeMaxDynamicSharedMemorySize, SMBIG);
    cudaFuncSetAttribute(pgemm<256, true, true, true>,
                         cudaFuncAttributeMaxDynamicSharedMemorySize, SMBIG);
    cudaFuncSetAttribute(pgemm<256, false, true, false>,
                         cudaFuncAttributeMaxDynamicSharedMemorySize, SMBIG);

    float scale = 1.0f / sqrtf((float)Dn);
    dim3 tb(32, 8);

    // operand preparation (fp16, weights transposed)
    cvt_kernel<<<(Tn * Dn) / 1024, 256>>>(x, xh);
    tc_kernel<<<dim3(Un / 32, Dn / 32, Hn), tb>>>(qw, qwT, Dn, Un);
    tc_kernel<<<dim3(Un / 32, Dn / 32, Hn), tb>>>(kw, kwT, Dn, Un);
    tc_kernel<<<dim3(Dn / 32, Dn / 32, Hn), tb>>>(vw, vwT, Dn, Dn);
    tc_kernel<<<dim3(Dn / 32, (Hn * Dn) / 32, 1), tb>>>(lw, lwT, Hn * Dn, Dn);
    tc_kernel<<<dim3(Fn / 32, Dn / 32, 1), tb>>>(w1, w1T, Dn, Fn);
    tc_kernel<<<dim3(Dn / 32, Fn / 32, 1), tb>>>(w2, w2T, Fn, Dn);

    // Q,K: [8192,64] = x @ qw[h]
    pgemm<64, true, false, false><<<dim3(1, Tn / 128, Hn), 256, SM64>>>(
        xh, qwT, nullptr, nullptr, Q,
        Dn, Dn, Dn, Un, 0, 0, (long long)Un * Dn, 0,
        (long long)Tn * Un, 0, 1, 1.0f);
    pgemm<64, true, false, false><<<dim3(1, Tn / 128, Hn), 256, SM64>>>(
        xh, kwT, nullptr, nullptr, K,
        Dn, Dn, Dn, Un, 0, 0, (long long)Un * Dn, 0,
        (long long)Tn * Un, 0, 1, 1.0f);

    // VT[h] = vwT[h] @ x^T : [512, 8192]
    pgemm<256, true, false, false><<<dim3(Tn / 256, Dn / 128, Hn), 256, SMBIG>>>(
        vwT, xh, nullptr, nullptr, VT,
        Dn, Dn, Dn, Tn, (long long)Dn * Dn, 0, 0, 0,
        (long long)Dn * Tn, 0, 1, 1.0f);

    // scores = scale * Q @ K^T : [1024,1024], K=64, out fp32
    pgemm<256, false, false, false><<<dim3(Sn / 256, Sn / 128, Hn * Bn), 256, SMBIG>>>(
        Q, K, nullptr, S, nullptr,
        Un, Un, Un, Sn,
        (long long)Tn * Un, (long long)Sn * Un,
        (long long)Tn * Un, (long long)Sn * Un,
        (long long)Bn * Sn * Sn, (long long)Sn * Sn, Bn, scale);

    softmax_kernel<<<Hn * Bn * Sn, 256>>>(S, P);

    // attn = P @ VT[h][:, b]^T -> concat Ac
    pgemm<256, true, false, false><<<dim3(Dn / 256, Sn / 128, Hn * Bn), 256, SMBIG>>>(
        P, VT, nullptr, nullptr, Ac,
        Sn, Sn, Tn, Hn * Dn,
        (long long)Bn * Sn * Sn, (long long)Sn * Sn,
        (long long)Dn * Tn, (long long)Sn,
        (long long)Dn, (long long)Sn * Hn * Dn, Bn, 1.0f);

    // mha = Ac @ lw : [8192,512], K=4096, out fp32
    pgemm<256, false, false, false><<<dim3(Dn / 256, Tn / 128, 1), 256, SMBIG>>>(
        Ac, lwT, nullptr, mha, nullptr,
        Hn * Dn, Hn * Dn, Hn * Dn, Dn, 0, 0, 0, 0, 0, 0, 1, 1.0f);

    add_ln_kernel<true><<<Tn, 128>>>(x, mha, g1, b1v, hb, hbh);

    // f1 = relu(hb @ w1 + b1) : [8192,2048]
    pgemm<256, true, true, true><<<dim3(Fn / 256, Tn / 128, 1), 256, SMBIG>>>(
        hbh, w1T, bb1, nullptr, f1,
        Dn, Dn, Dn, Fn, 0, 0, 0, 0, 0, 0, 1, 1.0f);

    // f2 = f1 @ w2 + b2 : [8192,512], K=2048, out fp32
    pgemm<256, false, true, false><<<dim3(Dn / 256, Tn / 128, 1), 256, SMBIG>>>(
        f1, w2T, bb2, f2, nullptr,
        Fn, Fn, Fn, Dn, 0, 0, 0, 0, 0, 0, 1, 1.0f);

    add_ln_kernel<false><<<Tn, 128>>>(hb, f2, g2, b2v, out, nullptr);
}

// round 11
// speedup vs baseline: 1.2025x; 1.2025x over previous
#include <cuda_runtime.h>
#include <cuda_fp16.h>
#include <cstdint>
#include <math.h>

#define Tn 8192
#define Sn 1024
#define Bn 8
#define Hn 8
#define Un 64
#define Dn 512
#define Fn 2048

// ---------------- scratch ----------------------------------------------------
__device__ __half g_xh[(size_t)Tn * Dn];
__device__ __half g_qwT[(size_t)Hn * Un * Dn];
__device__ __half g_kwT[(size_t)Hn * Un * Dn];
__device__ __half g_vwT[(size_t)Hn * Dn * Dn];
__device__ __half g_lwT[(size_t)Dn * Hn * Dn];
__device__ __half g_w1T[(size_t)Fn * Dn];
__device__ __half g_w2T[(size_t)Dn * Fn];
__device__ __half g_Q[(size_t)Hn * Tn * Un];
__device__ __half g_K[(size_t)Hn * Tn * Un];
__device__ __half g_VT[(size_t)Hn * Dn * Tn];
__device__ float  g_S[(size_t)Hn * Bn * Sn * Sn];
__device__ __half g_P[(size_t)Hn * Bn * Sn * Sn];
__device__ __half g_Ac[(size_t)Tn * Hn * Dn];
__device__ float  g_mha[(size_t)Tn * Dn];
__device__ float  g_hb[(size_t)Tn * Dn];
__device__ __half g_hbh[(size_t)Tn * Dn];
__device__ __half g_f1[(size_t)Tn * Fn];
__device__ float  g_f2[(size_t)Tn * Dn];

// ---------------- helpers ----------------------------------------------------
__device__ __forceinline__ uint32_t smem_u32(const void* p) {
    uint32_t a;
    asm("{ .reg .u64 t; cvta.to.shared.u64 t, %1; cvt.u32.u64 %0, t; }"
        : "=r"(a) : "l"(p));
    return a;
}
__device__ __forceinline__ void cp_async16(uint32_t s, const void* g) {
    asm volatile("cp.async.cg.shared.global [%0], [%1], 16;\n" :: "r"(s), "l"(g));
}
__device__ __forceinline__ void cp_commit() {
    asm volatile("cp.async.commit_group;\n" ::);
}
__device__ __forceinline__ void cp_wait2() {
    asm volatile("cp.async.wait_group 2;\n" ::);
}
__device__ __forceinline__ void ldsm4(uint32_t* r, uint32_t addr) {
    asm volatile("ldmatrix.sync.aligned.m8n8.x4.shared.b16 {%0,%1,%2,%3}, [%4];"
                 : "=r"(r[0]), "=r"(r[1]), "=r"(r[2]), "=r"(r[3]) : "r"(addr));
}
__device__ __forceinline__ void mma16816(float* c, const uint32_t* a,
                                         uint32_t b0, uint32_t b1) {
    asm volatile(
        "mma.sync.aligned.m16n8k16.row.col.f32.f16.f16.f32 "
        "{%0,%1,%2,%3}, {%4,%5,%6,%7}, {%8,%9}, {%0,%1,%2,%3};"
        : "+f"(c[0]), "+f"(c[1]), "+f"(c[2]), "+f"(c[3])
        : "r"(a[0]), "r"(a[1]), "r"(a[2]), "r"(a[3]), "r"(b0), "r"(b1));
}

// ---------------- pipelined fp16 HMMA GEMM -----------------------------------
// C[m,n] = alpha * sum_k A[m,k]*B[n,k] (+bias[n]) (opt relu).
// A,B fp16 row-major. M%128==0, N%TSN==0, K%32==0. 256 thr, warps 2m x 4n,
// warp tile 64 x (TSN/4). 4-stage cp.async ring, one __syncthreads per k-tile.
#define RSTR 80   // smem row stride bytes (64B data + 16B pad)

template <int TSN, bool OUTH, bool BIAS, bool RELU>
__global__ __launch_bounds__(256) void pgemm(
    const __half* __restrict__ A_, const __half* __restrict__ B_,
    const float* __restrict__ bias, float* __restrict__ Cf,
    __half* __restrict__ Ch,
    int K, int lda, int ldb, int ldc,
    long long sAh, long long sAb, long long sBh, long long sBb,
    long long sCh, long long sCb, int bdiv, float alpha)
{
    constexpr int WN = TSN / 4;       // 32 or 16
    constexpr int NT = WN / 8;        // 4 or 2
    constexpr int ABYT = 128 * RSTR;
    constexpr int BBYT = TSN * RSTR;
    constexpr int STAGE = ABYT + BBYT;

    extern __shared__ char sm[];
    uint32_t sb = smem_u32(sm);

    int tid = threadIdx.x, lane = tid & 31, wid = tid >> 5;
    int wm = wid & 1, wn = wid >> 1;

    int z = blockIdx.z;
    int h = z / bdiv, b = z % bdiv;
    const __half* Ab = A_ + h * sAh + b * sAb;
    const __half* Bb = B_ + h * sBh + b * sBb;

    long long m0 = (long long)blockIdx.y * 128;
    int n0 = blockIdx.x * TSN;

    // staging maps
    int arow = tid >> 1;
    uint32_t aoff = arow * RSTR + (tid & 1) * 32;
    const __half* gA = Ab + (m0 + arow) * (long long)lda + (tid & 1) * 16;
    uint32_t boff;
    const __half* gB;
    if (TSN == 128) {
        int brow = tid >> 1;
        boff = ABYT + brow * RSTR + (tid & 1) * 32;
        gB = Bb + (long long)(n0 + brow) * ldb + (tid & 1) * 16;
    } else {
        int brow = tid >> 2;
        boff = ABYT + brow * RSTR + (tid & 3) * 16;
        gB = Bb + (long long)(n0 + brow) * ldb + (tid & 3) * 8;
    }

    int lrow = lane & 15, lhalf = lane >> 4;
    uint32_t pAo = (wm * 64 + lrow) * RSTR + lhalf * 16;
    uint32_t pBo = ABYT + (wn * WN + lrow) * RSTR + lhalf * 16;

    float acc[4][NT][4];
#pragma unroll
    for (int i = 0; i < 4; i++)
#pragma unroll
        for (int j = 0; j < NT; j++)
#pragma unroll
            for (int q = 0; q < 4; q++) acc[i][j][q] = 0.0f;

    int ktiles = K / 32;

    auto load_stage = [&](int ktl, uint32_t sd) {
        long long ko = (long long)ktl * 32;
        cp_async16(sd + aoff, gA + ko);
        cp_async16(sd + aoff + 16, gA + ko + 8);
        if (TSN == 128) {
            cp_async16(sd + boff, gB + ko);
            cp_async16(sd + boff + 16, gB + ko + 8);
        } else {
            cp_async16(sd + boff, gB + ko);
        }
    };

    load_stage(0, sb);
    cp_commit();
    if (ktiles > 1) load_stage(1, sb + STAGE);
    cp_commit();

    for (int kt = 0; kt < ktiles; kt++) {
        int buf = kt & 3;
        if (kt + 2 < ktiles) load_stage(kt + 2, sb + ((kt + 2) & 3) * STAGE);
        cp_commit();
        cp_wait2();
        __syncthreads();

        uint32_t pA = sb + buf * STAGE + pAo;
        uint32_t pB = sb + buf * STAGE + pBo;
#pragma unroll
        for (int ks = 0; ks < 2; ks++) {
            uint32_t af[4][4];
#pragma unroll
            for (int mt = 0; mt < 4; mt++)
                ldsm4(af[mt], pA + mt * 16 * RSTR + ks * 32);
            uint32_t bf[NT / 2][4];
#pragma unroll
            for (int np = 0; np < NT / 2; np++)
                ldsm4(bf[np], pB + np * 16 * RSTR + ks * 32);
#pragma unroll
            for (int mt = 0; mt < 4; mt++)
#pragma unroll
                for (int np = 0; np < NT / 2; np++) {
                    mma16816(acc[mt][2 * np], af[mt], bf[np][0], bf[np][2]);
                    mma16816(acc[mt][2 * np + 1], af[mt], bf[np][1], bf[np][3]);
                }
        }
        // buffer reused 4 iterations later; syncthreads above suffices
    }

    // epilogue
    int g = lane >> 2, c2 = (lane & 3) * 2;
    long long hoff = h * sCh + b * sCb;
#pragma unroll
    for (int mt = 0; mt < 4; mt++) {
        long long r0 = m0 + wm * 64 + mt * 16 + g;
#pragma unroll
        for (int nt = 0; nt < NT; nt++) {
            int col = n0 + wn * WN + nt * 8 + c2;
            float v0 = acc[mt][nt][0] * alpha, v1 = acc[mt][nt][1] * alpha;
            float v2 = acc[mt][nt][2] * alpha, v3 = acc[mt][nt][3] * alpha;
            if (BIAS) {
                float b0 = bias[col], b1 = bias[col + 1];
                v0 += b0; v1 += b1; v2 += b0; v3 += b1;
            }
            if (RELU) {
                v0 = fmaxf(v0, 0.f); v1 = fmaxf(v1, 0.f);
                v2 = fmaxf(v2, 0.f); v3 = fmaxf(v3, 0.f);
            }
            if (OUTH) {
                *(__half2*)(Ch + hoff + r0 * ldc + col) = __floats2half2_rn(v0, v1);
                *(__half2*)(Ch + hoff + (r0 + 8) * ldc + col) = __floats2half2_rn(v2, v3);
            } else {
                float2 o0 = {v0, v1}, o1 = {v2, v3};
                *(float2*)(Cf + hoff + r0 * ldc + col) = o0;
                *(float2*)(Cf + hoff + (r0 + 8) * ldc + col) = o1;
            }
        }
    }
}

// ---------------- elementwise convert: fp32 -> fp16 --------------------------
__global__ __launch_bounds__(256) void cvt_kernel(
    const float* __restrict__ in, __half* __restrict__ o)
{
    long long i = (long long)blockIdx.x * 256 + threadIdx.x;
    float4 v = reinterpret_cast<const float4*>(in)[i];
    reinterpret_cast<__half2*>(o)[2 * i] = __floats2half2_rn(v.x, v.y);
    reinterpret_cast<__half2*>(o)[2 * i + 1] = __floats2half2_rn(v.z, v.w);
}

// ---------------- transpose+convert [Z][R][C] -> fp16 [Z][C][R] --------------
__global__ __launch_bounds__(256) void tc_kernel(
    const float* __restrict__ in, __half* __restrict__ o, int R, int C)
{
    __shared__ float t[32][33];
    const float* ib = in + (long long)blockIdx.z * R * C;
    long long ob = (long long)blockIdx.z * R * C;
    int c0 = blockIdx.x * 32, r0 = blockIdx.y * 32;
    int x = threadIdx.x, y = threadIdx.y;
#pragma unroll
    for (int i = 0; i < 32; i += 8)
        t[y + i][x] = ib[(long long)(r0 + y + i) * C + c0 + x];
    __syncthreads();
#pragma unroll
    for (int i = 0; i < 32; i += 8)
        o[ob + (long long)(c0 + y + i) * R + r0 + x] = __float2half_rn(t[x][y + i]);
}

// ---------------- softmax (row=1024) -> fp16, __expf + shuffle reductions ----
__global__ __launch_bounds__(256) void softmax_kernel(
    const float* __restrict__ S, __half* __restrict__ P)
{
    long long row = blockIdx.x;
    const float4* p = reinterpret_cast<const float4*>(S + row * Sn);
    int tid = threadIdx.x, lane = tid & 31, wid = tid >> 5;
    float4 v = p[tid];
    __shared__ float wred[8];

    float m = fmaxf(fmaxf(v.x, v.y), fmaxf(v.z, v.w));
#pragma unroll
    for (int o = 16; o; o >>= 1)
        m = fmaxf(m, __shfl_xor_sync(0xffffffffu, m, o));
    if (lane == 0) wred[wid] = m;
    __syncthreads();
    float rmax = wred[0];
#pragma unroll
    for (int i = 1; i < 8; i++) rmax = fmaxf(rmax, wred[i]);
    __syncthreads();

    v.x = __expf(v.x - rmax); v.y = __expf(v.y - rmax);
    v.z = __expf(v.z - rmax); v.w = __expf(v.w - rmax);
    float s = v.x + v.y + v.z + v.w;
#pragma unroll
    for (int o = 16; o; o >>= 1)
        s += __shfl_xor_sync(0xffffffffu, s, o);
    if (lane == 0) wred[wid] = s;
    __syncthreads();
    float tot = wred[0];
#pragma unroll
    for (int i = 1; i < 8; i++) tot += wred[i];

    float inv = __fdividef(1.0f, tot);
    __half2* ph = reinterpret_cast<__half2*>(P + row * Sn);
    ph[2 * tid] = __floats2half2_rn(v.x * inv, v.y * inv);
    ph[2 * tid + 1] = __floats2half2_rn(v.z * inv, v.w * inv);
}

// ---------------- residual add + LayerNorm (row=512), shuffle reductions -----
template <bool EMIT>
__global__ __launch_bounds__(128) void add_ln_kernel(
    const float* __restrict__ X, const float* __restrict__ Y,
    const float* __restrict__ gamma, const float* __restrict__ beta,
    float* __restrict__ out, __half* __restrict__ oh)
{
    long long row = blockIdx.x;
    int tid = threadIdx.x, lane = tid & 31, wid = tid >> 5;
    const float4* x4 = reinterpret_cast<const float4*>(X + row * Dn);
    const float4* y4 = reinterpret_cast<const float4*>(Y + row * Dn);
    float4 a = x4[tid], c = y4[tid];
    float v0 = a.x + c.x, v1 = a.y + c.y, v2 = a.z + c.z, v3 = a.w + c.w;
    __shared__ float ws[4], wq[4];
    float s = v0 + v1 + v2 + v3;
    float q = v0 * v0 + v1 * v1 + v2 * v2 + v3 * v3;
#pragma unroll
    for (int o = 16; o; o >>= 1) {
        s += __shfl_xor_sync(0xffffffffu, s, o);
        q += __shfl_xor_sync(0xffffffffu, q, o);
    }
    if (lane == 0) { ws[wid] = s; wq[wid] = q; }
    __syncthreads();
    float rs = ws[0] + ws[1] + ws[2] + ws[3];
    float rq = wq[0] + wq[1] + wq[2] + wq[3];
    float mean = rs * (1.0f / Dn);
    float var = rq * (1.0f / Dn) - mean * mean;
    float rstd = rsqrtf(var + 1e-3f);
    float4 g = reinterpret_cast<const float4*>(gamma)[tid];
    float4 bb = reinterpret_cast<const float4*>(beta)[tid];
    float4 o;
    o.x = g.x * (v0 - mean) * rstd + bb.x;
    o.y = g.y * (v1 - mean) * rstd + bb.y;
    o.z = g.z * (v2 - mean) * rstd + bb.z;
    o.w = g.w * (v3 - mean) * rstd + bb.w;
    reinterpret_cast<float4*>(out + row * Dn)[tid] = o;
    if (EMIT) {
        __half2* ph = reinterpret_cast<__half2*>(oh + row * Dn);
        ph[2 * tid] = __floats2half2_rn(o.x, o.y);
        ph[2 * tid + 1] = __floats2half2_rn(o.z, o.w);
    }
}

// ---------------- launch -----------------------------------------------------
extern "C" void kernel_launch(void* const* d_in, const int* in_sizes, int n_in,
                              void* d_out, int out_size)
{
    const float* x  = (const float*)d_in[0];
    const float* qw = (const float*)d_in[1];
    const float* kw = (const float*)d_in[2];
    const float* vw = (const float*)d_in[3];
    const float* lw = (const float*)d_in[4];
    const float* g1 = (const float*)d_in[5];
    const float* b1v= (const float*)d_in[6];
    const float* w1 = (const float*)d_in[7];
    const float* bb1= (const float*)d_in[8];
    const float* w2 = (const float*)d_in[9];
    const float* bb2= (const float*)d_in[10];
    const float* g2 = (const float*)d_in[11];
    const float* b2v= (const float*)d_in[12];
    float* out = (float*)d_out;

#define GA(p, s) cudaGetSymbolAddress((void**)&p, s)
    __half *xh, *qwT, *kwT, *vwT, *lwT, *w1T, *w2T;
    __half *Q, *K, *VT, *P, *Ac, *hbh, *f1;
    float *S, *mha, *hb, *f2;
    GA(xh, g_xh);
    GA(qwT, g_qwT); GA(kwT, g_kwT); GA(vwT, g_vwT); GA(lwT, g_lwT);
    GA(w1T, g_w1T); GA(w2T, g_w2T);
    GA(Q, g_Q); GA(K, g_K); GA(VT, g_VT);
    GA(P, g_P); GA(Ac, g_Ac); GA(hbh, g_hbh); GA(f1, g_f1);
    GA(S, g_S); GA(mha, g_mha); GA(hb, g_hb); GA(f2, g_f2);
#undef GA

    constexpr int SM128 = 4 * (128 * RSTR + 128 * RSTR); // 81920
    constexpr int SM64  = 4 * (128 * RSTR + 64 * RSTR);  // 61440
    cudaFuncSetAttribute(pgemm<64, true, false, false>,
                         cudaFuncAttributeMaxDynamicSharedMemorySize, SM64);
    cudaFuncSetAttribute(pgemm<128, true, false, false>,
                         cudaFuncAttributeMaxDynamicSharedMemorySize, SM128);
    cudaFuncSetAttribute(pgemm<128, false, false, false>,
                         cudaFuncAttributeMaxDynamicSharedMemorySize, SM128);
    cudaFuncSetAttribute(pgemm<128, true, true, true>,
                         cudaFuncAttributeMaxDynamicSharedMemorySize, SM128);
    cudaFuncSetAttribute(pgemm<128, false, true, false>,
                         cudaFuncAttributeMaxDynamicSharedMemorySize, SM128);

    float scale = 1.0f / sqrtf((float)Dn);
    dim3 tb(32, 8);

    // operand preparation (fp16, weights transposed)
    cvt_kernel<<<(Tn * Dn) / 1024, 256>>>(x, xh);
    tc_kernel<<<dim3(Un / 32, Dn / 32, Hn), tb>>>(qw, qwT, Dn, Un);
    tc_kernel<<<dim3(Un / 32, Dn / 32, Hn), tb>>>(kw, kwT, Dn, Un);
    tc_kernel<<<dim3(Dn / 32, Dn / 32, Hn), tb>>>(vw, vwT, Dn, Dn);
    tc_kernel<<<dim3(Dn / 32, (Hn * Dn) / 32, 1), tb>>>(lw, lwT, Hn * Dn, Dn);
    tc_kernel<<<dim3(Fn / 32, Dn / 32, 1), tb>>>(w1, w1T, Dn, Fn);
    tc_kernel<<<dim3(Dn / 32, Fn / 32, 1), tb>>>(w2, w2T, Fn, Dn);

    // Q,K: [8192,64] = x @ qw[h]
    pgemm<64, true, false, false><<<dim3(1, Tn / 128, Hn), 256, SM64>>>(
        xh, qwT, nullptr, nullptr, Q,
        Dn, Dn, Dn, Un, 0, 0, (long long)Un * Dn, 0,
        (long long)Tn * Un, 0, 1, 1.0f);
    pgemm<64, true, false, false><<<dim3(1, Tn / 128, Hn), 256, SM64>>>(
        xh, kwT, nullptr, nullptr, K,
        Dn, Dn, Dn, Un, 0, 0, (long long)Un * Dn, 0,
        (long long)Tn * Un, 0, 1, 1.0f);

    // VT[h] = vwT[h] @ x^T : [512, 8192]
    pgemm<128, true, false, false><<<dim3(Tn / 128, Dn / 128, Hn), 256, SM128>>>(
        vwT, xh, nullptr, nullptr, VT,
        Dn, Dn, Dn, Tn, (long long)Dn * Dn, 0, 0, 0,
        (long long)Dn * Tn, 0, 1, 1.0f);

    // scores = scale * Q @ K^T : [1024,1024], K=64, out fp32
    pgemm<128, false, false, false><<<dim3(Sn / 128, Sn / 128, Hn * Bn), 256, SM128>>>(
        Q, K, nullptr, S, nullptr,
        Un, Un, Un, Sn,
        (long long)Tn * Un, (long long)Sn * Un,
        (long long)Tn * Un, (long long)Sn * Un,
        (long long)Bn * Sn * Sn, (long long)Sn * Sn, Bn, scale);

    softmax_kernel<<<Hn * Bn * Sn, 256>>>(S, P);

    // attn = P @ VT[h][:, b]^T -> concat Ac
    pgemm<128, true, false, false><<<dim3(Dn / 128, Sn / 128, Hn * Bn), 256, SM128>>>(
        P, VT, nullptr, nullptr, Ac,
        Sn, Sn, Tn, Hn * Dn,
        (long long)Bn * Sn * Sn, (long long)Sn * Sn,
        (long long)Dn * Tn, (long long)Sn,
        (long long)Dn, (long long)Sn * Hn * Dn, Bn, 1.0f);

    // mha = Ac @ lw : [8192,512], K=4096, out fp32
    pgemm<128, false, false, false><<<dim3(Dn / 128, Tn / 128, 1), 256, SM128>>>(
        Ac, lwT, nullptr, mha, nullptr,
        Hn * Dn, Hn * Dn, Hn * Dn, Dn, 0, 0, 0, 0, 0, 0, 1, 1.0f);

    add_ln_kernel<true><<<Tn, 128>>>(x, mha, g1, b1v, hb, hbh);

    // f1 = relu(hb @ w1 + b1) : [8192,2048]
    pgemm<128, true, true, true><<<dim3(Fn / 128, Tn / 128, 1), 256, SM128>>>(
        hbh, w1T, bb1, nullptr, f1,
        Dn, Dn, Dn, Fn, 0, 0, 0, 0, 0, 0, 1, 1.0f);

    // f2 = f1 @ w2 + b2 : [8192,512], K=2048, out fp32
    pgemm<128, false, true, false><<<dim3(Dn / 128, Tn / 128, 1), 256, SM128>>>(
        f1, w2T, bb2, f2, nullptr,
        Fn, Fn, Fn, Dn, 0, 0, 0, 0, 0, 0, 1, 1.0f);

    add_ln_kernel<false><<<Tn, 128>>>(hb, f2, g2, b2v, out, nullptr);
}

// round 12
// speedup vs baseline: 1.2034x; 1.0008x over previous
#include <cuda_runtime.h>
#include <cuda_fp16.h>
#include <cstdint>
#include <math.h>

#define Tn 8192
#define Sn 1024
#define Bn 8
#define Hn 8
#define Un 64
#define Dn 512
#define Fn 2048

// ---------------- scratch ----------------------------------------------------
__device__ __half g_xh[(size_t)Tn * Dn];
__device__ __half g_qwT[(size_t)Hn * Un * Dn];
__device__ __half g_kwT[(size_t)Hn * Un * Dn];
__device__ __half g_vwT[(size_t)Hn * Dn * Dn];
__device__ __half g_lwT[(size_t)Dn * Hn * Dn];
__device__ __half g_w1T[(size_t)Fn * Dn];
__device__ __half g_w2T[(size_t)Dn * Fn];
__device__ __half g_Q[(size_t)Hn * Tn * Un];
__device__ __half g_K[(size_t)Hn * Tn * Un];
__device__ __half g_VT[(size_t)Hn * Dn * Tn];
__device__ __half g_S[(size_t)Hn * Bn * Sn * Sn];   // fp16 logits
__device__ __half g_P[(size_t)Hn * Bn * Sn * Sn];
__device__ __half g_Ac[(size_t)Tn * Hn * Dn];
__device__ float  g_mha[(size_t)Tn * Dn];
__device__ float  g_hb[(size_t)Tn * Dn];
__device__ __half g_hbh[(size_t)Tn * Dn];
__device__ __half g_f1[(size_t)Tn * Fn];
__device__ float  g_f2[(size_t)Tn * Dn];

// ---------------- helpers ----------------------------------------------------
__device__ __forceinline__ uint32_t smem_u32(const void* p) {
    uint32_t a;
    asm("{ .reg .u64 t; cvta.to.shared.u64 t, %1; cvt.u32.u64 %0, t; }"
        : "=r"(a) : "l"(p));
    return a;
}
__device__ __forceinline__ void cp_async16(uint32_t s, const void* g) {
    asm volatile("cp.async.cg.shared.global [%0], [%1], 16;\n" :: "r"(s), "l"(g));
}
__device__ __forceinline__ void cp_commit() {
    asm volatile("cp.async.commit_group;\n" ::);
}
__device__ __forceinline__ void cp_wait2() {
    asm volatile("cp.async.wait_group 2;\n" ::);
}
__device__ __forceinline__ void ldsm4(uint32_t* r, uint32_t addr) {
    asm volatile("ldmatrix.sync.aligned.m8n8.x4.shared.b16 {%0,%1,%2,%3}, [%4];"
                 : "=r"(r[0]), "=r"(r[1]), "=r"(r[2]), "=r"(r[3]) : "r"(addr));
}
__device__ __forceinline__ void mma16816(float* c, const uint32_t* a,
                                         uint32_t b0, uint32_t b1) {
    asm volatile(
        "mma.sync.aligned.m16n8k16.row.col.f32.f16.f16.f32 "
        "{%0,%1,%2,%3}, {%4,%5,%6,%7}, {%8,%9}, {%0,%1,%2,%3};"
        : "+f"(c[0]), "+f"(c[1]), "+f"(c[2]), "+f"(c[3])
        : "r"(a[0]), "r"(a[1]), "r"(a[2]), "r"(a[3]), "r"(b0), "r"(b1));
}

// ---------------- pipelined fp16 HMMA GEMM -----------------------------------
// C[m,n] = alpha * sum_k A[m,k]*B[n,k] (+bias[n]) (opt relu).
// A,B fp16 row-major. M%128==0, N%TSN==0, K%32==0. 256 thr, warps 2m x 4n,
// warp tile 64 x (TSN/4). 4-stage cp.async ring, one __syncthreads per k-tile.
#define RSTR 80   // smem row stride bytes (64B data + 16B pad)

template <int TSN, bool OUTH, bool BIAS, bool RELU>
__global__ __launch_bounds__(256, 2) void pgemm(
    const __half* __restrict__ A_, const __half* __restrict__ B_,
    const float* __restrict__ bias, float* __restrict__ Cf,
    __half* __restrict__ Ch,
    int K, int lda, int ldb, int ldc,
    long long sAh, long long sAb, long long sBh, long long sBb,
    long long sCh, long long sCb, int bdiv, float alpha)
{
    constexpr int WN = TSN / 4;       // 32 or 16
    constexpr int NT = WN / 8;        // 4 or 2
    constexpr int ABYT = 128 * RSTR;
    constexpr int BBYT = TSN * RSTR;
    constexpr int STAGE = ABYT + BBYT;

    extern __shared__ char sm[];
    uint32_t sb = smem_u32(sm);

    int tid = threadIdx.x, lane = tid & 31, wid = tid >> 5;
    int wm = wid & 1, wn = wid >> 1;

    int z = blockIdx.z;
    int h = z / bdiv, b = z % bdiv;
    const __half* Ab = A_ + h * sAh + b * sAb;
    const __half* Bb = B_ + h * sBh + b * sBb;

    long long m0 = (long long)blockIdx.y * 128;
    int n0 = blockIdx.x * TSN;

    // staging maps
    int arow = tid >> 1;
    uint32_t aoff = arow * RSTR + (tid & 1) * 32;
    const __half* gA = Ab + (m0 + arow) * (long long)lda + (tid & 1) * 16;
    uint32_t boff;
    const __half* gB;
    if (TSN == 128) {
        int brow = tid >> 1;
        boff = ABYT + brow * RSTR + (tid & 1) * 32;
        gB = Bb + (long long)(n0 + brow) * ldb + (tid & 1) * 16;
    } else {
        int brow = tid >> 2;
        boff = ABYT + brow * RSTR + (tid & 3) * 16;
        gB = Bb + (long long)(n0 + brow) * ldb + (tid & 3) * 8;
    }

    int lrow = lane & 15, lhalf = lane >> 4;
    uint32_t pAo = (wm * 64 + lrow) * RSTR + lhalf * 16;
    uint32_t pBo = ABYT + (wn * WN + lrow) * RSTR + lhalf * 16;

    float acc[4][NT][4];
#pragma unroll
    for (int i = 0; i < 4; i++)
#pragma unroll
        for (int j = 0; j < NT; j++)
#pragma unroll
            for (int q = 0; q < 4; q++) acc[i][j][q] = 0.0f;

    int ktiles = K / 32;

    auto load_stage = [&](int ktl, uint32_t sd) {
        long long ko = (long long)ktl * 32;
        cp_async16(sd + aoff, gA + ko);
        cp_async16(sd + aoff + 16, gA + ko + 8);
        if (TSN == 128) {
            cp_async16(sd + boff, gB + ko);
            cp_async16(sd + boff + 16, gB + ko + 8);
        } else {
            cp_async16(sd + boff, gB + ko);
        }
    };

    load_stage(0, sb);
    cp_commit();
    if (ktiles > 1) load_stage(1, sb + STAGE);
    cp_commit();

    for (int kt = 0; kt < ktiles; kt++) {
        int buf = kt & 3;
        if (kt + 2 < ktiles) load_stage(kt + 2, sb + ((kt + 2) & 3) * STAGE);
        cp_commit();
        cp_wait2();
        __syncthreads();

        uint32_t pA = sb + buf * STAGE + pAo;
        uint32_t pB = sb + buf * STAGE + pBo;
#pragma unroll
        for (int ks = 0; ks < 2; ks++) {
            uint32_t af[4][4];
#pragma unroll
            for (int mt = 0; mt < 4; mt++)
                ldsm4(af[mt], pA + mt * 16 * RSTR + ks * 32);
            uint32_t bf[NT / 2][4];
#pragma unroll
            for (int np = 0; np < NT / 2; np++)
                ldsm4(bf[np], pB + np * 16 * RSTR + ks * 32);
#pragma unroll
            for (int mt = 0; mt < 4; mt++)
#pragma unroll
                for (int np = 0; np < NT / 2; np++) {
                    mma16816(acc[mt][2 * np], af[mt], bf[np][0], bf[np][2]);
                    mma16816(acc[mt][2 * np + 1], af[mt], bf[np][1], bf[np][3]);
                }
        }
        // buffer reused 4 iterations later; syncthreads above suffices
    }

    // epilogue
    int g = lane >> 2, c2 = (lane & 3) * 2;
    long long hoff = h * sCh + b * sCb;
#pragma unroll
    for (int mt = 0; mt < 4; mt++) {
        long long r0 = m0 + wm * 64 + mt * 16 + g;
#pragma unroll
        for (int nt = 0; nt < NT; nt++) {
            int col = n0 + wn * WN + nt * 8 + c2;
            float v0 = acc[mt][nt][0] * alpha, v1 = acc[mt][nt][1] * alpha;
            float v2 = acc[mt][nt][2] * alpha, v3 = acc[mt][nt][3] * alpha;
            if (BIAS) {
                float b0 = bias[col], b1 = bias[col + 1];
                v0 += b0; v1 += b1; v2 += b0; v3 += b1;
            }
            if (RELU) {
                v0 = fmaxf(v0, 0.f); v1 = fmaxf(v1, 0.f);
                v2 = fmaxf(v2, 0.f); v3 = fmaxf(v3, 0.f);
            }
            if (OUTH) {
                *(__half2*)(Ch + hoff + r0 * ldc + col) = __floats2half2_rn(v0, v1);
                *(__half2*)(Ch + hoff + (r0 + 8) * ldc + col) = __floats2half2_rn(v2, v3);
            } else {
                float2 o0 = {v0, v1}, o1 = {v2, v3};
                *(float2*)(Cf + hoff + r0 * ldc + col) = o0;
                *(float2*)(Cf + hoff + (r0 + 8) * ldc + col) = o1;
            }
        }
    }
}

// ---------------- elementwise convert: fp32 -> fp16 --------------------------
__global__ __launch_bounds__(256) void cvt_kernel(
    const float* __restrict__ in, __half* __restrict__ o)
{
    long long i = (long long)blockIdx.x * 256 + threadIdx.x;
    float4 v = reinterpret_cast<const float4*>(in)[i];
    reinterpret_cast<__half2*>(o)[2 * i] = __floats2half2_rn(v.x, v.y);
    reinterpret_cast<__half2*>(o)[2 * i + 1] = __floats2half2_rn(v.z, v.w);
}

// ---------------- transpose+convert [Z][R][C] -> fp16 [Z][C][R] --------------
__global__ __launch_bounds__(256) void tc_kernel(
    const float* __restrict__ in, __half* __restrict__ o, int R, int C)
{
    __shared__ float t[32][33];
    const float* ib = in + (long long)blockIdx.z * R * C;
    long long ob = (long long)blockIdx.z * R * C;
    int c0 = blockIdx.x * 32, r0 = blockIdx.y * 32;
    int x = threadIdx.x, y = threadIdx.y;
#pragma unroll
    for (int i = 0; i < 32; i += 8)
        t[y + i][x] = ib[(long long)(r0 + y + i) * C + c0 + x];
    __syncthreads();
#pragma unroll
    for (int i = 0; i < 32; i += 8)
        o[ob + (long long)(c0 + y + i) * R + r0 + x] = __float2half_rn(t[x][y + i]);
}

// ---------------- softmax (row=1024), fp16 in -> fp16 out --------------------
__global__ __launch_bounds__(256) void softmax_kernel(
    const __half* __restrict__ S, __half* __restrict__ P)
{
    long long row = blockIdx.x;
    int tid = threadIdx.x, lane = tid & 31, wid = tid >> 5;
    const __half2* ps = reinterpret_cast<const __half2*>(S + row * Sn);
    float2 a = __half22float2(ps[2 * tid]);
    float2 bq = __half22float2(ps[2 * tid + 1]);
    float vx = a.x, vy = a.y, vz = bq.x, vw = bq.y;
    __shared__ float wred[8];

    float m = fmaxf(fmaxf(vx, vy), fmaxf(vz, vw));
#pragma unroll
    for (int o = 16; o; o >>= 1)
        m = fmaxf(m, __shfl_xor_sync(0xffffffffu, m, o));
    if (lane == 0) wred[wid] = m;
    __syncthreads();
    float rmax = wred[0];
#pragma unroll
    for (int i = 1; i < 8; i++) rmax = fmaxf(rmax, wred[i]);
    __syncthreads();

    vx = __expf(vx - rmax); vy = __expf(vy - rmax);
    vz = __expf(vz - rmax); vw = __expf(vw - rmax);
    float s = vx + vy + vz + vw;
#pragma unroll
    for (int o = 16; o; o >>= 1)
        s += __shfl_xor_sync(0xffffffffu, s, o);
    if (lane == 0) wred[wid] = s;
    __syncthreads();
    float tot = wred[0];
#pragma unroll
    for (int i = 1; i < 8; i++) tot += wred[i];

    float inv = __fdividef(1.0f, tot);
    __half2* ph = reinterpret_cast<__half2*>(P + row * Sn);
    ph[2 * tid] = __floats2half2_rn(vx * inv, vy * inv);
    ph[2 * tid + 1] = __floats2half2_rn(vz * inv, vw * inv);
}

// ---------------- residual add + LayerNorm (row=512), shuffle reductions -----
template <bool EMIT>
__global__ __launch_bounds__(128) void add_ln_kernel(
    const float* __restrict__ X, const float* __restrict__ Y,
    const float* __restrict__ gamma, const float* __restrict__ beta,
    float* __restrict__ out, __half* __restrict__ oh)
{
    long long row = blockIdx.x;
    int tid = threadIdx.x, lane = tid & 31, wid = tid >> 5;
    const float4* x4 = reinterpret_cast<const float4*>(X + row * Dn);
    const float4* y4 = reinterpret_cast<const float4*>(Y + row * Dn);
    float4 a = x4[tid], c = y4[tid];
    float v0 = a.x + c.x, v1 = a.y + c.y, v2 = a.z + c.z, v3 = a.w + c.w;
    __shared__ float ws[4], wq[4];
    float s = v0 + v1 + v2 + v3;
    float q = v0 * v0 + v1 * v1 + v2 * v2 + v3 * v3;
#pragma unroll
    for (int o = 16; o; o >>= 1) {
        s += __shfl_xor_sync(0xffffffffu, s, o);
        q += __shfl_xor_sync(0xffffffffu, q, o);
    }
    if (lane == 0) { ws[wid] = s; wq[wid] = q; }
    __syncthreads();
    float rs = ws[0] + ws[1] + ws[2] + ws[3];
    float rq = wq[0] + wq[1] + wq[2] + wq[3];
    float mean = rs * (1.0f / Dn);
    float var = rq * (1.0f / Dn) - mean * mean;
    float rstd = rsqrtf(var + 1e-3f);
    float4 g = reinterpret_cast<const float4*>(gamma)[tid];
    float4 bb = reinterpret_cast<const float4*>(beta)[tid];
    float4 o;
    o.x = g.x * (v0 - mean) * rstd + bb.x;
    o.y = g.y * (v1 - mean) * rstd + bb.y;
    o.z = g.z * (v2 - mean) * rstd + bb.z;
    o.w = g.w * (v3 - mean) * rstd + bb.w;
    reinterpret_cast<float4*>(out + row * Dn)[tid] = o;
    if (EMIT) {
        __half2* ph = reinterpret_cast<__half2*>(oh + row * Dn);
        ph[2 * tid] = __floats2half2_rn(o.x, o.y);
        ph[2 * tid + 1] = __floats2half2_rn(o.z, o.w);
    }
}

// ---------------- launch -----------------------------------------------------
extern "C" void kernel_launch(void* const* d_in, const int* in_sizes, int n_in,
                              void* d_out, int out_size)
{
    const float* x  = (const float*)d_in[0];
    const float* qw = (const float*)d_in[1];
    const float* kw = (const float*)d_in[2];
    const float* vw = (const float*)d_in[3];
    const float* lw = (const float*)d_in[4];
    const float* g1 = (const float*)d_in[5];
    const float* b1v= (const float*)d_in[6];
    const float* w1 = (const float*)d_in[7];
    const float* bb1= (const float*)d_in[8];
    const float* w2 = (const float*)d_in[9];
    const float* bb2= (const float*)d_in[10];
    const float* g2 = (const float*)d_in[11];
    const float* b2v= (const float*)d_in[12];
    float* out = (float*)d_out;

#define GA(p, s) cudaGetSymbolAddress((void**)&p, s)
    __half *xh, *qwT, *kwT, *vwT, *lwT, *w1T, *w2T;
    __half *Q, *K, *VT, *S, *P, *Ac, *hbh, *f1;
    float *mha, *hb, *f2;
    GA(xh, g_xh);
    GA(qwT, g_qwT); GA(kwT, g_kwT); GA(vwT, g_vwT); GA(lwT, g_lwT);
    GA(w1T, g_w1T); GA(w2T, g_w2T);
    GA(Q, g_Q); GA(K, g_K); GA(VT, g_VT);
    GA(S, g_S); GA(P, g_P); GA(Ac, g_Ac); GA(hbh, g_hbh); GA(f1, g_f1);
    GA(mha, g_mha); GA(hb, g_hb); GA(f2, g_f2);
#undef GA

    constexpr int SM128 = 4 * (128 * RSTR + 128 * RSTR); // 81920
    constexpr int SM64  = 4 * (128 * RSTR + 64 * RSTR);  // 61440
    cudaFuncSetAttribute(pgemm<64, true, false, false>,
                         cudaFuncAttributeMaxDynamicSharedMemorySize, SM64);
    cudaFuncSetAttribute(pgemm<128, true, false, false>,
                         cudaFuncAttributeMaxDynamicSharedMemorySize, SM128);
    cudaFuncSetAttribute(pgemm<128, false, false, false>,
                         cudaFuncAttributeMaxDynamicSharedMemorySize, SM128);
    cudaFuncSetAttribute(pgemm<128, true, true, true>,
                         cudaFuncAttributeMaxDynamicSharedMemorySize, SM128);
    cudaFuncSetAttribute(pgemm<128, false, true, false>,
                         cudaFuncAttributeMaxDynamicSharedMemorySize, SM128);

    float scale = 1.0f / sqrtf((float)Dn);
    dim3 tb(32, 8);

    // operand preparation (fp16, weights transposed)
    cvt_kernel<<<(Tn * Dn) / 1024, 256>>>(x, xh);
    tc_kernel<<<dim3(Un / 32, Dn / 32, Hn), tb>>>(qw, qwT, Dn, Un);
    tc_kernel<<<dim3(Un / 32, Dn / 32, Hn), tb>>>(kw, kwT, Dn, Un);
    tc_kernel<<<dim3(Dn / 32, Dn / 32, Hn), tb>>>(vw, vwT, Dn, Dn);
    tc_kernel<<<dim3(Dn / 32, (Hn * Dn) / 32, 1), tb>>>(lw, lwT, Hn * Dn, Dn);
    tc_kernel<<<dim3(Fn / 32, Dn / 32, 1), tb>>>(w1, w1T, Dn, Fn);
    tc_kernel<<<dim3(Dn / 32, Fn / 32, 1), tb>>>(w2, w2T, Fn, Dn);

    // Q,K: [8192,64] = x @ qw[h]
    pgemm<64, true, false, false><<<dim3(1, Tn / 128, Hn), 256, SM64>>>(
        xh, qwT, nullptr, nullptr, Q,
        Dn, Dn, Dn, Un, 0, 0, (long long)Un * Dn, 0,
        (long long)Tn * Un, 0, 1, 1.0f);
    pgemm<64, true, false, false><<<dim3(1, Tn / 128, Hn), 256, SM64>>>(
        xh, kwT, nullptr, nullptr, K,
        Dn, Dn, Dn, Un, 0, 0, (long long)Un * Dn, 0,
        (long long)Tn * Un, 0, 1, 1.0f);

    // VT[h] = vwT[h] @ x^T : [512, 8192]
    pgemm<128, true, false, false><<<dim3(Tn / 128, Dn / 128, Hn), 256, SM128>>>(
        vwT, xh, nullptr, nullptr, VT,
        Dn, Dn, Dn, Tn, (long long)Dn * Dn, 0, 0, 0,
        (long long)Dn * Tn, 0, 1, 1.0f);

    // scores = scale * Q @ K^T : [1024,1024], K=64, out fp16
    pgemm<128, true, false, false><<<dim3(Sn / 128, Sn / 128, Hn * Bn), 256, SM128>>>(
        Q, K, nullptr, nullptr, S,
        Un, Un, Un, Sn,
        (long long)Tn * Un, (long long)Sn * Un,
        (long long)Tn * Un, (long long)Sn * Un,
        (long long)Bn * Sn * Sn, (long long)Sn * Sn, Bn, scale);

    softmax_kernel<<<Hn * Bn * Sn, 256>>>(S, P);

    // attn = P @ VT[h][:, b]^T -> concat Ac
    pgemm<128, true, false, false><<<dim3(Dn / 128, Sn / 128, Hn * Bn), 256, SM128>>>(
        P, VT, nullptr, nullptr, Ac,
        Sn, Sn, Tn, Hn * Dn,
        (long long)Bn * Sn * Sn, (long long)Sn * Sn,
        (long long)Dn * Tn, (long long)Sn,
        (long long)Dn, (long long)Sn * Hn * Dn, Bn, 1.0f);

    // mha = Ac @ lw : [8192,512], K=4096, out fp32
    pgemm<128, false, false, false><<<dim3(Dn / 128, Tn / 128, 1), 256, SM128>>>(
        Ac, lwT, nullptr, mha, nullptr,
        Hn * Dn, Hn * Dn, Hn * Dn, Dn, 0, 0, 0, 0, 0, 0, 1, 1.0f);

    add_ln_kernel<true><<<Tn, 128>>>(x, mha, g1, b1v, hb, hbh);

    // f1 = relu(hb @ w1 + b1) : [8192,2048]
    pgemm<128, true, true, true><<<dim3(Fn / 128, Tn / 128, 1), 256, SM128>>>(
        hbh, w1T, bb1, nullptr, f1,
        Dn, Dn, Dn, Fn, 0, 0, 0, 0, 0, 0, 1, 1.0f);

    // f2 = f1 @ w2 + b2 : [8192,512], K=2048, out fp32
    pgemm<128, false, true, false><<<dim3(Dn / 128, Tn / 128, 1), 256, SM128>>>(
        f1, w2T, bb2, f2, nullptr,
        Fn, Fn, Fn, Dn, 0, 0, 0, 0, 0, 0, 1, 1.0f);

    add_ln_kernel<false><<<Tn, 128>>>(hb, f2, g2, b2v, out, nullptr);
}